// round 2
// baseline (speedup 1.0000x reference)
#include <cuda_runtime.h>
#include <math.h>

// Problem constants (fixed by the dataset: B=4, H=W=256, C=64, r=8)
#define HW      65536
#define CMID    64
#define RNUM    8
#define MAXB    4

// -------- device scratch (no allocations allowed) --------
__device__ float g_xmean[MAXB][4];          // per-batch channel means of [rgb, edge]
__device__ float g_M[MAXB][RNUM][CMID][4];  // fused kernel: K @ W1   (64x4 per (b,r))
__device__ float g_V[MAXB][RNUM][CMID];     // fused bias:   K @ b1   (64 per (b,r))
__device__ float g_G[RNUM][4];              // fused guide:  Wg @ W1  (8x4)
__device__ float g_gb[RNUM];                // fused guide bias: Wg@b1 + bg

// =====================================================================
// Kernel 0: channel means of the 4 input planes per batch.
// grid = 4*B blocks, block (b, ch). 4 MB read total — trivial.
// =====================================================================
__global__ void k_means(const float* __restrict__ rgb,
                        const float* __restrict__ edge)
{
    int b  = blockIdx.x >> 2;
    int ch = blockIdx.x & 3;
    const float* src = (ch < 3) ? (rgb + ((size_t)b * 3 + ch) * HW)
                                : (edge + (size_t)b * HW);
    const float4* s4 = (const float4*)src;

    float s = 0.0f;
    for (int i = threadIdx.x; i < HW / 4; i += 256) {
        float4 v = s4[i];
        s += (v.x + v.y) + (v.z + v.w);
    }
    __shared__ float red[256];
    red[threadIdx.x] = s;
    __syncthreads();
    for (int off = 128; off > 0; off >>= 1) {
        if (threadIdx.x < off) red[threadIdx.x] += red[threadIdx.x + off];
        __syncthreads();
    }
    if (threadIdx.x == 0)
        g_xmean[b][ch] = red[0] * (1.0f / (float)HW);
}

// =====================================================================
// Kernel P: generate per-(b,r) dynamic kernel K (64x64) and immediately
// fold it:  M = K @ W1 (64x4),  v = K @ b1 (64).
// Also computes the batch-independent fused guide G = Wg@W1, gb = Wg@b1+bg.
// grid = B*RNUM blocks of 256 threads. Tiny (<2us).
// =====================================================================
__global__ void k_prep(const float* __restrict__ W1,  const float* __restrict__ b1,
                       const float* __restrict__ Wk1, const float* __restrict__ bk1,
                       const float* __restrict__ Wk2, const float* __restrict__ bk2,
                       const float* __restrict__ Wg,  const float* __restrict__ bg)
{
    int b = blockIdx.x >> 3;
    int r = blockIdx.x & 7;
    int t = threadIdx.x;

    __shared__ float gsh[CMID];
    __shared__ float tgsh[RNUM];

    // g[c] = b1[c] + sum_i W1[c,i] * xmean[b,i]
    if (t < CMID) {
        float xm0 = g_xmean[b][0], xm1 = g_xmean[b][1];
        float xm2 = g_xmean[b][2], xm3 = g_xmean[b][3];
        gsh[t] = b1[t] + W1[t*4+0]*xm0 + W1[t*4+1]*xm1
                       + W1[t*4+2]*xm2 + W1[t*4+3]*xm3;
    }
    __syncthreads();

    // tg[i] = sigmoid( bk1[r*8+i] + g . Wk1[r*8+i, :] )
    if (t < RNUM) {
        int j = r * RNUM + t;
        float s = bk1[j];
        const float* wk = Wk1 + (size_t)j * CMID;
        #pragma unroll 8
        for (int c = 0; c < CMID; c++) s += gsh[c] * wk[c];
        tgsh[t] = 1.0f / (1.0f + expf(-s));
    }
    __syncthreads();

    // thread o (< 64): build K row o on the fly, fold into M/v
    if (t < CMID) {
        int o = t;
        float tg[8];
        #pragma unroll
        for (int i = 0; i < 8; i++) tg[i] = tgsh[i];

        float m0 = 0.f, m1 = 0.f, m2 = 0.f, m3 = 0.f, vv = 0.f;
        #pragma unroll 4
        for (int c = 0; c < CMID; c++) {
            int midx = o * CMID + c;
            const float* w2 = Wk2 + ((size_t)r * (CMID*CMID) + midx) * RNUM;
            float kv = bk2[(size_t)r * (CMID*CMID) + midx];
            #pragma unroll
            for (int i = 0; i < 8; i++) kv += tg[i] * w2[i];
            m0 += kv * W1[c*4+0];
            m1 += kv * W1[c*4+1];
            m2 += kv * W1[c*4+2];
            m3 += kv * W1[c*4+3];
            vv += kv * b1[c];
        }
        g_M[b][r][o][0] = m0;  g_M[b][r][o][1] = m1;
        g_M[b][r][o][2] = m2;  g_M[b][r][o][3] = m3;
        g_V[b][r][o]    = vv;
    }

    // fused guide (batch-independent) — do it once in block 0
    if (blockIdx.x == 0 && t >= 64 && t < 64 + RNUM) {
        int j = t - 64;
        const float* wg = Wg + (size_t)j * CMID;
        float a0 = 0.f, a1 = 0.f, a2 = 0.f, a3 = 0.f, vb = 0.f;
        for (int c = 0; c < CMID; c++) {
            float w = wg[c];
            a0 += w * W1[c*4+0];
            a1 += w * W1[c*4+1];
            a2 += w * W1[c*4+2];
            a3 += w * W1[c*4+3];
            vb += w * b1[c];
        }
        g_G[j][0] = a0; g_G[j][1] = a1; g_G[j][2] = a2; g_G[j][3] = a3;
        g_gb[j]   = vb + bg[j];
    }
}

// =====================================================================
// Kernel M: main per-pixel pass.
//   x = (r,g,b,edge) 4 floats;
//   guide[r] = G[r].x4 + gb[r]   (8x4 fused)  -> argmax (first-max ties)
//   out[o]   = M[b,rmax][o].x4 + v[b,rmax][o] (64 outputs)
// Region-divergent smem reads use padded strides (260 / 68 words) so the
// 8 regions land on disjoint 4-bank groups -> conflict-free 128B accesses.
// grid = B*256 blocks x 256 threads, 1 pixel/thread, coalesced I/O.
// =====================================================================
__global__ void __launch_bounds__(256)
k_main(const float* __restrict__ rgb,
       const float* __restrict__ edge,
       float* __restrict__ out)
{
    __shared__ __align__(16) float Ms[RNUM * 260]; // region stride 260 words (16B aligned, bank 4r)
    __shared__ __align__(16) float Vs[RNUM * 68];  // region stride 68 words  (16B aligned, bank 4r)
    __shared__ float4 Gs[RNUM];
    __shared__ float  gbs[RNUM];

    int b = blockIdx.x >> 8;           // 256 blocks per batch image
    int t = threadIdx.x;

    // stage fused per-batch tables
    const float* Mg = &g_M[b][0][0][0];          // 2048 contiguous floats
    for (int k = t; k < RNUM * CMID * 4; k += 256)
        Ms[(k >> 8) * 260 + (k & 255)] = Mg[k];
    const float* Vg = &g_V[b][0][0];             // 512 contiguous floats
    for (int k = t; k < RNUM * CMID; k += 256)
        Vs[(k >> 6) * 68 + (k & 63)] = Vg[k];
    if (t < RNUM) {
        Gs[t]  = *(const float4*)&g_G[t][0];
        gbs[t] = g_gb[t];
    }
    __syncthreads();

    int p = ((blockIdx.x & 255) << 8) + t;       // pixel index within the image
    const float* rp = rgb + (size_t)b * 3 * HW;
    float x0 = rp[p];
    float x1 = rp[HW + p];
    float x2 = rp[2 * HW + p];
    float x3 = edge[(size_t)b * HW + p];

    // guide + argmax (strictly-greater keeps first max, matching jnp.argmax)
    float best;
    int   br = 0;
    {
        float4 G0 = Gs[0];
        best = gbs[0] + G0.x * x0 + G0.y * x1 + G0.z * x2 + G0.w * x3;
        #pragma unroll
        for (int r = 1; r < RNUM; r++) {
            float4 Gr = Gs[r];
            float gv = gbs[r] + Gr.x * x0 + Gr.y * x1 + Gr.z * x2 + Gr.w * x3;
            if (gv > best) { best = gv; br = r; }
        }
    }

    const float* Mr = &Ms[br * 260];
    const float* Vr = &Vs[br * 68];
    float* op = out + (size_t)b * CMID * HW + p;

    #pragma unroll
    for (int o4 = 0; o4 < 16; o4++) {
        float4 vv = *(const float4*)(Vr + o4 * 4);
        float4 m0 = *(const float4*)(Mr + (o4 * 4 + 0) * 4);
        float4 m1 = *(const float4*)(Mr + (o4 * 4 + 1) * 4);
        float4 m2 = *(const float4*)(Mr + (o4 * 4 + 2) * 4);
        float4 m3 = *(const float4*)(Mr + (o4 * 4 + 3) * 4);
        op[(size_t)(o4 * 4 + 0) * HW] = vv.x + m0.x*x0 + m0.y*x1 + m0.z*x2 + m0.w*x3;
        op[(size_t)(o4 * 4 + 1) * HW] = vv.y + m1.x*x0 + m1.y*x1 + m1.z*x2 + m1.w*x3;
        op[(size_t)(o4 * 4 + 2) * HW] = vv.z + m2.x*x0 + m2.y*x1 + m2.z*x2 + m2.w*x3;
        op[(size_t)(o4 * 4 + 3) * HW] = vv.w + m3.x*x0 + m3.y*x1 + m3.z*x2 + m3.w*x3;
    }
}

// =====================================================================
extern "C" void kernel_launch(void* const* d_in, const int* in_sizes, int n_in,
                              void* d_out, int out_size)
{
    const float* rgb  = (const float*)d_in[0];
    const float* edge = (const float*)d_in[1];
    const float* W1   = (const float*)d_in[2];
    const float* b1   = (const float*)d_in[3];
    const float* Wk1  = (const float*)d_in[4];
    const float* bk1  = (const float*)d_in[5];
    const float* Wk2  = (const float*)d_in[6];
    const float* bk2  = (const float*)d_in[7];
    const float* Wg   = (const float*)d_in[8];
    const float* bg   = (const float*)d_in[9];
    float* out = (float*)d_out;

    int B = in_sizes[1] / HW;      // edge is (B,1,H,W)
    if (B < 1) B = 1;
    if (B > MAXB) B = MAXB;

    k_means<<<4 * B, 256>>>(rgb, edge);
    k_prep <<<B * RNUM, 256>>>(W1, b1, Wk1, bk1, Wk2, bk2, Wg, bg);
    k_main <<<B * 256, 256>>>(rgb, edge, out);
}

// round 3
// speedup vs baseline: 1.8296x; 1.8296x over previous
#include <cuda_runtime.h>
#include <math.h>

// Problem constants (fixed by the dataset: B=4, H=W=256, C=64, r=8)
#define HW      65536
#define CMID    64
#define RNUM    8
#define MAXB    4
#define NCHUNK  16   // mean-reduction chunks per plane

// -------- device scratch (no allocations allowed) --------
__device__ float g_part[MAXB * 4][NCHUNK];    // partial plane sums
__device__ float g_Mt[MAXB][RNUM][4][CMID];   // fused kernel TRANSPOSED: Mt[b][r][i][o]
__device__ float g_V[MAXB][RNUM][CMID];       // fused bias: K @ b1
__device__ float g_G[RNUM][4];                // fused guide:  Wg @ W1
__device__ float g_gb[RNUM];                  // fused guide bias

// ---------------- packed f32x2 helpers ----------------
__device__ __forceinline__ unsigned long long fma2(unsigned long long a,
                                                   unsigned long long b,
                                                   unsigned long long c)
{
    unsigned long long d;
    asm("fma.rn.f32x2 %0, %1, %2, %3;" : "=l"(d) : "l"(a), "l"(b), "l"(c));
    return d;
}
__device__ __forceinline__ unsigned long long pack2(float x)
{
    unsigned long long d;
    unsigned int u = __float_as_uint(x);
    asm("mov.b64 %0, {%1, %1};" : "=l"(d) : "r"(u));
    return d;
}
__device__ __forceinline__ void unpack2(unsigned long long v, float& lo, float& hi)
{
    unsigned int a, b;
    asm("mov.b64 {%0, %1}, %2;" : "=r"(a), "=r"(b) : "l"(v));
    lo = __uint_as_float(a);
    hi = __uint_as_float(b);
}

// =====================================================================
// Kernel 0: partial channel sums. grid = 4*B*NCHUNK blocks (full chip).
// block -> (plane, chunk); plane = b*4+ch. Each block sums HW/NCHUNK floats.
// =====================================================================
__global__ void __launch_bounds__(256)
k_means_part(const float* __restrict__ rgb, const float* __restrict__ edge)
{
    int plane = blockIdx.x >> 4;          // 4*B planes
    int chunk = blockIdx.x & (NCHUNK - 1);
    int b  = plane >> 2;
    int ch = plane & 3;
    const float* src = (ch < 3) ? (rgb + ((size_t)b * 3 + ch) * HW)
                                : (edge + (size_t)b * HW);
    const float4* s4 = (const float4*)(src) + chunk * (HW / NCHUNK / 4);

    float s = 0.0f;
    #pragma unroll
    for (int k = 0; k < HW / NCHUNK / 4 / 256; k++) {   // 4 iterations
        float4 v = s4[k * 256 + threadIdx.x];
        s += (v.x + v.y) + (v.z + v.w);
    }
    // warp then block reduce
    #pragma unroll
    for (int off = 16; off > 0; off >>= 1)
        s += __shfl_xor_sync(0xffffffffu, s, off);
    __shared__ float red[8];
    if ((threadIdx.x & 31) == 0) red[threadIdx.x >> 5] = s;
    __syncthreads();
    if (threadIdx.x == 0) {
        float t = 0.f;
        #pragma unroll
        for (int w = 0; w < 8; w++) t += red[w];
        g_part[plane][chunk] = t;
    }
}

// =====================================================================
// Kernel P: reduce means, generate per-(b,r) kernel K and fold it into
//   Mt = (K @ W1)^T (4x64)  and  v = K @ b1 (64).
// grid = B*RNUM blocks of 256 threads; thread = (o = t>>2, q = t&3),
// each quad covers c in [16q, 16q+16), reduced with shfl.
// =====================================================================
__global__ void __launch_bounds__(256)
k_prep(const float* __restrict__ W1,  const float* __restrict__ b1,
       const float* __restrict__ Wk1, const float* __restrict__ bk1,
       const float* __restrict__ Wk2, const float* __restrict__ bk2,
       const float* __restrict__ Wg,  const float* __restrict__ bg)
{
    int b = blockIdx.x >> 3;
    int r = blockIdx.x & 7;
    int t = threadIdx.x;

    __shared__ float w1s[CMID * 4];
    __shared__ float b1s[CMID];
    __shared__ float xm[4];
    __shared__ float gsh[CMID];
    __shared__ float tgsh[RNUM];

    if (t < CMID * 4) w1s[t] = W1[t];
    if (t >= 128 && t < 128 + CMID) b1s[t - 128] = b1[t - 128];
    if (t >= 224 && t < 228) {                    // xmean from partials
        int ch = t - 224;
        float s = 0.f;
        #pragma unroll
        for (int j = 0; j < NCHUNK; j++) s += g_part[b * 4 + ch][j];
        xm[ch] = s * (1.0f / (float)HW);
    }
    __syncthreads();

    if (t < CMID)
        gsh[t] = b1s[t] + w1s[t*4+0]*xm[0] + w1s[t*4+1]*xm[1]
                        + w1s[t*4+2]*xm[2] + w1s[t*4+3]*xm[3];
    __syncthreads();

    if (t < RNUM) {
        int j = r * RNUM + t;
        float s = bk1[j];
        const float* wk = Wk1 + (size_t)j * CMID;
        #pragma unroll 8
        for (int c = 0; c < CMID; c++) s += gsh[c] * wk[c];
        tgsh[t] = 1.0f / (1.0f + expf(-s));
    }
    __syncthreads();

    {
        int o = t >> 2;
        int q = t & 3;
        float tg[8];
        #pragma unroll
        for (int i = 0; i < 8; i++) tg[i] = tgsh[i];

        float m0 = 0.f, m1 = 0.f, m2 = 0.f, m3 = 0.f, vv = 0.f;
        const size_t rbase = (size_t)r * (CMID * CMID);
        #pragma unroll 4
        for (int cc = 0; cc < 16; cc++) {
            int c = q * 16 + cc;
            size_t midx = rbase + o * CMID + c;
            const float4* w2 = (const float4*)(Wk2 + midx * RNUM);
            float4 wa = w2[0], wb = w2[1];
            float kv = bk2[midx]
                     + tg[0]*wa.x + tg[1]*wa.y + tg[2]*wa.z + tg[3]*wa.w
                     + tg[4]*wb.x + tg[5]*wb.y + tg[6]*wb.z + tg[7]*wb.w;
            m0 += kv * w1s[c*4+0];
            m1 += kv * w1s[c*4+1];
            m2 += kv * w1s[c*4+2];
            m3 += kv * w1s[c*4+3];
            vv += kv * b1s[c];
        }
        #pragma unroll
        for (int off = 1; off < 4; off <<= 1) {
            m0 += __shfl_xor_sync(0xffffffffu, m0, off);
            m1 += __shfl_xor_sync(0xffffffffu, m1, off);
            m2 += __shfl_xor_sync(0xffffffffu, m2, off);
            m3 += __shfl_xor_sync(0xffffffffu, m3, off);
            vv += __shfl_xor_sync(0xffffffffu, vv, off);
        }
        if (q == 0) {
            g_Mt[b][r][0][o] = m0;
            g_Mt[b][r][1][o] = m1;
            g_Mt[b][r][2][o] = m2;
            g_Mt[b][r][3][o] = m3;
            g_V[b][r][o]     = vv;
        }
    }

    // fused guide (batch-independent) — block 0, one warp
    if (blockIdx.x == 0 && t >= 192 && t < 192 + RNUM) {
        int j = t - 192;
        const float* wg = Wg + (size_t)j * CMID;
        float a0 = 0.f, a1 = 0.f, a2 = 0.f, a3 = 0.f, vb = 0.f;
        for (int c = 0; c < CMID; c++) {
            float w = wg[c];
            a0 += w * w1s[c*4+0];
            a1 += w * w1s[c*4+1];
            a2 += w * w1s[c*4+2];
            a3 += w * w1s[c*4+3];
            vb += w * b1s[c];
        }
        g_G[j][0] = a0; g_G[j][1] = a1; g_G[j][2] = a2; g_G[j][3] = a3;
        g_gb[j]   = vb + bg[j];
    }
}

// =====================================================================
// Kernel M: main pass, 4 pixels/thread, float4 I/O, transposed-M smem,
// packed fma.rn.f32x2 math. grid = B*64 blocks x 256 threads.
//   smem Mt: region stride 260 floats (float4-slot = 65r + k, injective mod 32)
//   smem V : region stride 68  floats (float4-slot = 17r + k, injective mod 32)
// =====================================================================
__global__ void __launch_bounds__(256)
k_main(const float* __restrict__ rgb,
       const float* __restrict__ edge,
       float* __restrict__ out)
{
    __shared__ __align__(16) float Ms[RNUM * 260];
    __shared__ __align__(16) float Vs[RNUM * 68];
    __shared__ float4 Gs[RNUM];
    __shared__ float  gbs[RNUM];

    int b = blockIdx.x >> 6;           // 64 blocks per batch image
    int t = threadIdx.x;

    // stage fused per-batch tables (Mt is already transposed in global)
    const float* Mg = &g_Mt[b][0][0][0];          // 2048 contiguous floats
    #pragma unroll
    for (int k0 = 0; k0 < RNUM * CMID * 4; k0 += 256) {
        int k = k0 + t;
        Ms[(k >> 8) * 260 + (k & 255)] = Mg[k];
    }
    const float* Vg = &g_V[b][0][0];              // 512 contiguous floats
    #pragma unroll
    for (int k0 = 0; k0 < RNUM * CMID; k0 += 256) {
        int k = k0 + t;
        Vs[(k >> 6) * 68 + (k & 63)] = Vg[k];
    }
    if (t < RNUM) {
        Gs[t]  = *(const float4*)&g_G[t][0];
        gbs[t] = g_gb[t];
    }
    __syncthreads();

    int idx = ((blockIdx.x & 63) << 8) + t;       // float4 index within plane
    const float4* rp4 = (const float4*)(rgb + (size_t)b * 3 * HW);
    const float4* ep4 = (const float4*)(edge + (size_t)b * HW);
    float4 xv0 = rp4[idx];
    float4 xv1 = rp4[HW / 4 + idx];
    float4 xv2 = rp4[2 * (HW / 4) + idx];
    float4 xv3 = ep4[idx];

    // per-pixel inputs: xs[j][i] = input channel i of pixel j
    float xs[4][4];
    xs[0][0]=xv0.x; xs[1][0]=xv0.y; xs[2][0]=xv0.z; xs[3][0]=xv0.w;
    xs[0][1]=xv1.x; xs[1][1]=xv1.y; xs[2][1]=xv1.z; xs[3][1]=xv1.w;
    xs[0][2]=xv2.x; xs[1][2]=xv2.y; xs[2][2]=xv2.z; xs[3][2]=xv2.w;
    xs[0][3]=xv3.x; xs[1][3]=xv3.y; xs[2][3]=xv3.z; xs[3][3]=xv3.w;

    // guide + argmax per pixel (strict > keeps first max, matches jnp.argmax)
    const float* Mr[4];
    const float* Vr[4];
    #pragma unroll
    for (int j = 0; j < 4; j++) {
        float4 G0 = Gs[0];
        float best = gbs[0] + G0.x*xs[j][0] + G0.y*xs[j][1]
                            + G0.z*xs[j][2] + G0.w*xs[j][3];
        int br = 0;
        #pragma unroll
        for (int r = 1; r < RNUM; r++) {
            float4 Gr = Gs[r];
            float gv = gbs[r] + Gr.x*xs[j][0] + Gr.y*xs[j][1]
                              + Gr.z*xs[j][2] + Gr.w*xs[j][3];
            if (gv > best) { best = gv; br = r; }
        }
        Mr[j] = &Ms[br * 260];
        Vr[j] = &Vs[br * 68];
    }

    // packed broadcasts of inputs
    unsigned long long xb[4][4];
    #pragma unroll
    for (int j = 0; j < 4; j++)
        #pragma unroll
        for (int i = 0; i < 4; i++)
            xb[j][i] = pack2(xs[j][i]);

    float* op = out + (size_t)b * CMID * HW + (size_t)idx * 4;

    #pragma unroll 4
    for (int o4 = 0; o4 < 16; o4++) {
        float ov[4][4];                            // [cc][px]
        #pragma unroll
        for (int j = 0; j < 4; j++) {
            ulonglong2 vv = *(const ulonglong2*)(Vr[j] + o4 * 4);
            unsigned long long r0 = vv.x, r1 = vv.y;
            #pragma unroll
            for (int i = 0; i < 4; i++) {
                ulonglong2 m = *(const ulonglong2*)(Mr[j] + i * 64 + o4 * 4);
                r0 = fma2(m.x, xb[j][i], r0);
                r1 = fma2(m.y, xb[j][i], r1);
            }
            unpack2(r0, ov[0][j], ov[1][j]);
            unpack2(r1, ov[2][j], ov[3][j]);
        }
        #pragma unroll
        for (int cc = 0; cc < 4; cc++) {
            float4 s = make_float4(ov[cc][0], ov[cc][1], ov[cc][2], ov[cc][3]);
            *(float4*)(op + (size_t)(o4 * 4 + cc) * HW) = s;
        }
    }
}

// =====================================================================
extern "C" void kernel_launch(void* const* d_in, const int* in_sizes, int n_in,
                              void* d_out, int out_size)
{
    const float* rgb  = (const float*)d_in[0];
    const float* edge = (const float*)d_in[1];
    const float* W1   = (const float*)d_in[2];
    const float* b1   = (const float*)d_in[3];
    const float* Wk1  = (const float*)d_in[4];
    const float* bk1  = (const float*)d_in[5];
    const float* Wk2  = (const float*)d_in[6];
    const float* bk2  = (const float*)d_in[7];
    const float* Wg   = (const float*)d_in[8];
    const float* bg   = (const float*)d_in[9];
    float* out = (float*)d_out;

    int B = in_sizes[1] / HW;      // edge is (B,1,H,W)
    if (B < 1) B = 1;
    if (B > MAXB) B = MAXB;

    k_means_part<<<4 * B * NCHUNK, 256>>>(rgb, edge);
    k_prep      <<<B * RNUM,       256>>>(W1, b1, Wk1, bk1, Wk2, bk2, Wg, bg);
    k_main      <<<B * 64,         256>>>(rgb, edge, out);
}